// round 6
// baseline (speedup 1.0000x reference)
#include <cuda_runtime.h>
#include <cuda_fp16.h>
#include <cstdint>

#define NN   4096
#define DIN  128
#define HD   128
#define NE   131072
#define TOTE (NE + NN)
#define NEG  0.2f
#define G4   512

__device__ float g_h[NN * 512];
__device__ float g_asrc[NN * 4];
__device__ float g_adst[NN * 4];
__device__ int   g_cnt[NN];
__device__ int   g_off[NN + 1];
__device__ int   g_cur[NN];
__device__ int   g_srcs[TOTE];
__device__ float g_g[NN * HD];
__device__ float g_xg[(NN + 1) * G4];   // [t][4*unit+gate], +1 row slack for prefetch
__device__ __half g_xa[NN * 384];
__device__ __half g_xb[NN * 384];

__device__ __forceinline__ unsigned pack_h2(float x, float y) {
    __half2 h = __floats2half2_rn(x, y);
    return *reinterpret_cast<unsigned*>(&h);
}

__device__ __forceinline__ void mma16816(float* d, const unsigned* a, unsigned b0, unsigned b1) {
    asm volatile(
        "mma.sync.aligned.m16n8k16.row.col.f32.f16.f16.f32 "
        "{%0,%1,%2,%3}, {%4,%5,%6,%7}, {%8,%9}, {%0,%1,%2,%3};\n"
        : "+f"(d[0]), "+f"(d[1]), "+f"(d[2]), "+f"(d[3])
        : "r"(a[0]), "r"(a[1]), "r"(a[2]), "r"(a[3]), "r"(b0), "r"(b1));
}

__global__ void zero_cnt_kernel() {
    int i = blockIdx.x * blockDim.x + threadIdx.x;
    if (i < NN) g_cnt[i] = 0;
}

// ---- generic tiled SGEMM: C = A(MxK) @ B (+bias +bias2); PERM packs LSTM gate layout ----
template <bool TRANSB, bool PERM>
__global__ __launch_bounds__(256)
void gemm_kernel(const float* __restrict__ A, const float* __restrict__ B,
                 const float* __restrict__ bias, const float* __restrict__ bias2,
                 float* __restrict__ C, int M, int N, int K) {
    const int BK = 16;
    __shared__ float As[64][BK + 1];
    __shared__ float Bs[BK][64 + 1];
    int tid = threadIdx.x;
    int tx = tid & 15, ty = tid >> 4;
    int row0 = blockIdx.y * 64, col0 = blockIdx.x * 64;
    float acc[4][4];
#pragma unroll
    for (int r = 0; r < 4; r++)
#pragma unroll
        for (int c = 0; c < 4; c++) acc[r][c] = 0.f;

    for (int k0 = 0; k0 < K; k0 += BK) {
#pragma unroll
        for (int l = 0; l < 4; l++) {
            int idx = tid + l * 256;
            int m = idx >> 4, k = idx & 15;
            As[m][k] = A[(size_t)(row0 + m) * K + (k0 + k)];
        }
#pragma unroll
        for (int l = 0; l < 4; l++) {
            int idx = tid + l * 256;
            if (!TRANSB) {
                int k = idx >> 6, nn = idx & 63;
                Bs[k][nn] = (col0 + nn < N) ? B[(size_t)(k0 + k) * N + (col0 + nn)] : 0.f;
            } else {
                int nn = idx >> 4, k = idx & 15;
                Bs[k][nn] = (col0 + nn < N) ? B[(size_t)(col0 + nn) * K + (k0 + k)] : 0.f;
            }
        }
        __syncthreads();
#pragma unroll
        for (int k = 0; k < BK; k++) {
            float a[4], b[4];
#pragma unroll
            for (int r = 0; r < 4; r++) a[r] = As[ty * 4 + r][k];
#pragma unroll
            for (int c = 0; c < 4; c++) b[c] = Bs[k][tx * 4 + c];
#pragma unroll
            for (int r = 0; r < 4; r++)
#pragma unroll
                for (int c = 0; c < 4; c++) acc[r][c] += a[r] * b[c];
        }
        __syncthreads();
    }
#pragma unroll
    for (int r = 0; r < 4; r++) {
        int row = row0 + ty * 4 + r;
#pragma unroll
        for (int c = 0; c < 4; c++) {
            int col = col0 + tx * 4 + c;
            if (col < N) {
                float v = acc[r][c];
                if (bias)  v += bias[col];
                if (bias2) v += bias2[col];
                int oc = PERM ? ((col & 127) * 4 + (col >> 7)) : col;
                C[(size_t)row * N + oc] = v;
            }
        }
    }
}

// ---- attention logits ----
__global__ void a_kernel(const float* __restrict__ att_src,
                         const float* __restrict__ att_dst) {
    int n = blockIdx.x, tid = threadIdx.x;
    float hv = g_h[(size_t)n * 512 + tid];
    float ps = hv * att_src[tid];
    float pd = hv * att_dst[tid];
#pragma unroll
    for (int o = 16; o > 0; o >>= 1) {
        ps += __shfl_down_sync(0xffffffffu, ps, o);
        pd += __shfl_down_sync(0xffffffffu, pd, o);
    }
    __shared__ float sps[16], spd[16];
    int w = tid >> 5;
    if ((tid & 31) == 0) { sps[w] = ps; spd[w] = pd; }
    __syncthreads();
    if (tid < 4) {
        g_asrc[n * 4 + tid] = sps[tid * 4] + sps[tid * 4 + 1] + sps[tid * 4 + 2] + sps[tid * 4 + 3];
        g_adst[n * 4 + tid] = spd[tid * 4] + spd[tid * 4 + 1] + spd[tid * 4 + 2] + spd[tid * 4 + 3];
    }
}

__global__ void count_kernel(const int* __restrict__ ei) {
    int i = blockIdx.x * blockDim.x + threadIdx.x;
    if (i < NE) atomicAdd(&g_cnt[ei[NE + i]], 1);
    if (i < NN) atomicAdd(&g_cnt[i], 1);
}

__global__ void scan_kernel() {
    __shared__ int s[1024];
    int tid = threadIdx.x;
    int c[4]; int sum = 0;
#pragma unroll
    for (int i = 0; i < 4; i++) { c[i] = g_cnt[tid * 4 + i]; sum += c[i]; }
    s[tid] = sum;
    __syncthreads();
    for (int off = 1; off < 1024; off <<= 1) {
        int v = s[tid];
        int add = (tid >= off) ? s[tid - off] : 0;
        __syncthreads();
        s[tid] = v + add;
        __syncthreads();
    }
    int run = (tid == 0) ? 0 : s[tid - 1];
#pragma unroll
    for (int i = 0; i < 4; i++) {
        g_off[tid * 4 + i] = run;
        g_cur[tid * 4 + i] = run;
        run += c[i];
    }
    if (tid == 1023) g_off[NN] = run;
}

__global__ void scatter_kernel(const int* __restrict__ ei) {
    int i = blockIdx.x * blockDim.x + threadIdx.x;
    if (i < NE) {
        int d = ei[NE + i];
        g_srcs[atomicAdd(&g_cur[d], 1)] = ei[i];
    }
    if (i < NN) g_srcs[atomicAdd(&g_cur[i], 1)] = i;
}

// ---- GAT softmax + aggregate ----
#define CHUNK 512
__global__ __launch_bounds__(512)
void gat_agg_kernel(const float* __restrict__ b_gat) {
    int n = blockIdx.x, tid = threadIdx.x;
    int beg = g_off[n], end = g_off[n + 1];
    int deg = end - beg;

    __shared__ int   ssrc[CHUNK];
    __shared__ float salpha[CHUNK * 4];
    __shared__ float red[512];
    __shared__ float m_sh[4], rs_sh[4];

    int hh = tid & 3;
    float adst = g_adst[n * 4 + hh];
    float mx = -1e30f;
    for (int e = tid >> 2; e < deg; e += 128) {
        int s = g_srcs[beg + e];
        float v = g_asrc[s * 4 + hh] + adst;
        v = v >= 0.f ? v : NEG * v;
        mx = fmaxf(mx, v);
    }
    red[tid] = mx;
    __syncthreads();
    for (int s = 256; s >= 4; s >>= 1) {
        if (tid < s) red[tid] = fmaxf(red[tid], red[tid + s]);
        __syncthreads();
    }
    if (tid < 4) m_sh[tid] = red[tid];
    __syncthreads();

    float m = m_sh[hh];
    float ssum = 0.f;
    for (int e = tid >> 2; e < deg; e += 128) {
        int s = g_srcs[beg + e];
        float v = g_asrc[s * 4 + hh] + adst;
        v = v >= 0.f ? v : NEG * v;
        ssum += __expf(v - m);
    }
    __syncthreads();
    red[tid] = ssum;
    __syncthreads();
    for (int s = 256; s >= 4; s >>= 1) {
        if (tid < s) red[tid] += red[tid + s];
        __syncthreads();
    }
    if (tid < 4) rs_sh[tid] = 1.0f / (red[tid] + 1e-16f);
    __syncthreads();

    int head = tid >> 7;
    float acc = 0.f;
    float4 ad4 = *reinterpret_cast<const float4*>(&g_adst[n * 4]);
    float m0 = m_sh[0], m1 = m_sh[1], m2 = m_sh[2], m3 = m_sh[3];
    float r0 = rs_sh[0], r1 = rs_sh[1], r2 = rs_sh[2], r3 = rs_sh[3];

    for (int base = 0; base < deg; base += CHUNK) {
        int cnt = min(CHUNK, deg - base);
        __syncthreads();
        if (tid < cnt) {
            int s = g_srcs[beg + base + tid];
            ssrc[tid] = s;
            float4 as4 = *reinterpret_cast<const float4*>(&g_asrc[s * 4]);
            float e0 = as4.x + ad4.x; e0 = e0 >= 0.f ? e0 : NEG * e0;
            float e1 = as4.y + ad4.y; e1 = e1 >= 0.f ? e1 : NEG * e1;
            float e2 = as4.z + ad4.z; e2 = e2 >= 0.f ? e2 : NEG * e2;
            float e3 = as4.w + ad4.w; e3 = e3 >= 0.f ? e3 : NEG * e3;
            salpha[tid * 4 + 0] = __expf(e0 - m0) * r0;
            salpha[tid * 4 + 1] = __expf(e1 - m1) * r1;
            salpha[tid * 4 + 2] = __expf(e2 - m2) * r2;
            salpha[tid * 4 + 3] = __expf(e3 - m3) * r3;
        }
        __syncthreads();
#pragma unroll 4
        for (int e = 0; e < cnt; e++)
            acc += salpha[e * 4 + head] * g_h[(size_t)ssrc[e] * 512 + tid];
    }
    __syncthreads();
    red[tid] = acc;
    __syncthreads();
    if (tid < HD) {
        float s = red[tid] + red[128 + tid] + red[256 + tid] + red[384 + tid];
        float gv = s * 0.25f + b_gat[tid];
        g_g[(size_t)n * HD + tid] = gv > 0.f ? gv : 0.f;
    }
}

// ---- LSTM: dual-pipe (HMMA on K[0,64) + HFMA2 on K[64,128)), gate-interleaved ----
// Warp w owns permuted rows [32w, 32w+32); W''[R] = W_hh[(R&3)*128 + (R>>2)].
// Thread tid = row R = 4*unit+gate. Epilogue = proven round-3 style (smem gact,
// float4 gather, 2 barriers).
__global__ __launch_bounds__(512, 1)
void lstm_kernel(const float* __restrict__ Whh, float* __restrict__ emb_out) {
    __shared__ __align__(16) __half hsh[128];
    __shared__ __align__(16) float gact[512];
    int tid = threadIdx.x;
    int w = tid >> 5, lane = tid & 31;
    int grp = lane >> 2, t2 = (lane & 3) * 2;
    int gate = lane & 3;

    // HMMA A fragments: K columns 0..63 (4 k-chunks), gate-interleaved rows
    unsigned a[2][4][4];
#pragma unroll
    for (int mt = 0; mt < 2; mt++) {
        int rb = w * 32 + mt * 16;
#pragma unroll
        for (int kc = 0; kc < 4; kc++) {
            int cb = kc * 16;
            int r0 = rb + grp, r1 = rb + grp + 8;
            const float* row0 = Whh + (size_t)((r0 & 3) * 128 + (r0 >> 2)) * 128;
            const float* row1 = Whh + (size_t)((r1 & 3) * 128 + (r1 >> 2)) * 128;
            a[mt][kc][0] = pack_h2(row0[cb + t2],     row0[cb + t2 + 1]);
            a[mt][kc][1] = pack_h2(row1[cb + t2],     row1[cb + t2 + 1]);
            a[mt][kc][2] = pack_h2(row0[cb + t2 + 8], row0[cb + t2 + 9]);
            a[mt][kc][3] = pack_h2(row1[cb + t2 + 8], row1[cb + t2 + 9]);
        }
    }
    // HFMA2 weights for this thread's own row (K columns 64..127)
    const float* myrow = Whh + (size_t)((tid & 3) * 128 + (tid >> 2)) * 128;
    __half2 wv[32];
#pragma unroll
    for (int q = 0; q < 32; q++)
        wv[q] = __floats2half2_rn(myrow[64 + 2 * q], myrow[65 + 2 * q]);

    if (tid < 64) reinterpret_cast<__half2*>(hsh)[tid] = __floats2half2_rn(0.f, 0.f);
    float c = 0.f;
    __syncthreads();

    float xg = g_xg[tid];
#pragma unroll 1
    for (int t = 0; t < NN; t++) {
        // tensor pipe: K 0..63
        float d0[4] = {0.f, 0.f, 0.f, 0.f};
        float d1[4] = {0.f, 0.f, 0.f, 0.f};
#pragma unroll
        for (int kc = 0; kc < 4; kc++) {
            unsigned b0 = *reinterpret_cast<const unsigned*>(&hsh[kc * 16 + t2]);
            unsigned b1 = *reinterpret_cast<const unsigned*>(&hsh[kc * 16 + t2 + 8]);
            mma16816(d0, a[0][kc], b0, b1);
            mma16816(d1, a[1][kc], b0, b1);
        }
        // fma pipe: K 64..127 for this thread's own row
        __half2 hacc[8];
#pragma unroll
        for (int i = 0; i < 8; i++) hacc[i] = __floats2half2_rn(0.f, 0.f);
        const uint4* hv = reinterpret_cast<const uint4*>(&hsh[64]);
#pragma unroll
        for (int q = 0; q < 8; q++) {
            uint4 vv = hv[q];
            __half2 h0 = *reinterpret_cast<__half2*>(&vv.x);
            __half2 h1 = *reinterpret_cast<__half2*>(&vv.y);
            __half2 h2 = *reinterpret_cast<__half2*>(&vv.z);
            __half2 h3 = *reinterpret_cast<__half2*>(&vv.w);
            hacc[(4 * q + 0) & 7] = __hfma2(wv[4 * q + 0], h0, hacc[(4 * q + 0) & 7]);
            hacc[(4 * q + 1) & 7] = __hfma2(wv[4 * q + 1], h1, hacc[(4 * q + 1) & 7]);
            hacc[(4 * q + 2) & 7] = __hfma2(wv[4 * q + 2], h2, hacc[(4 * q + 2) & 7]);
            hacc[(4 * q + 3) & 7] = __hfma2(wv[4 * q + 3], h3, hacc[(4 * q + 3) & 7]);
        }
        float hsum = 0.f;
#pragma unroll
        for (int i = 0; i < 8; i++) {
            float2 f = __half22float2(hacc[i]);
            hsum += f.x + f.y;
        }
        float xgn = g_xg[(size_t)(t + 1) * 512 + tid];
        // select column 0 of mma result so lane l holds its row's partial
        int src = (lane & 7) * 4;
        float s00 = __shfl_sync(0xffffffffu, d0[0], src);
        float s02 = __shfl_sync(0xffffffffu, d0[2], src);
        float s10 = __shfl_sync(0xffffffffu, d1[0], src);
        float s12 = __shfl_sync(0xffffffffu, d1[2], src);
        float v = (lane & 16) ? ((lane & 8) ? s12 : s10) : ((lane & 8) ? s02 : s00);
        float z = v + hsum + xg;
        float act;
        if (gate == 2) act = __fdividef(2.f, 1.f + __expf(-2.f * z)) - 1.f;
        else           act = __fdividef(1.f, 1.f + __expf(-z));
        gact[tid] = act;
        __syncthreads();
        if (tid < 128) {
            float4 g4 = *reinterpret_cast<const float4*>(&gact[tid * 4]);
            c = g4.y * c + g4.x * g4.z;
            float th = __fdividef(2.f, 1.f + __expf(-2.f * c)) - 1.f;
            float hn = g4.w * th;
            emb_out[(size_t)t * HD + tid] = hn;
            hsh[tid] = __float2half_rn(hn);
        }
        __syncthreads();
        xg = xgn;
    }
}

// ---- normalize + pack split-fp16 for corr ----
__global__ void xn_pack_kernel(const float* __restrict__ emb) {
    int n = blockIdx.x, tid = threadIdx.x;
    float v = emb[(size_t)n * HD + tid];
    float ss = v * v;
#pragma unroll
    for (int o = 16; o > 0; o >>= 1) ss += __shfl_down_sync(0xffffffffu, ss, o);
    __shared__ float sw[4];
    __shared__ float rsh;
    if ((tid & 31) == 0) sw[tid >> 5] = ss;
    __syncthreads();
    if (tid == 0) rsh = 1.0f / fmaxf(sqrtf(sw[0] + sw[1] + sw[2] + sw[3]), 1e-12f);
    __syncthreads();
    float xv = v * rsh;
    __half hi = __float2half_rn(xv);
    __half lo = __float2half_rn(xv - __half2float(hi));
    size_t base = (size_t)n * 384;
    g_xa[base + tid]       = hi;
    g_xa[base + 128 + tid] = lo;
    g_xa[base + 256 + tid] = hi;
    g_xb[base + tid]       = hi;
    g_xb[base + 128 + tid] = hi;
    g_xb[base + 256 + tid] = lo;
}

// ---- corr = xa @ xb^T via HMMA, K=384 (split-fp16 exact) ----
__global__ __launch_bounds__(256, 2)
void corr_kernel(float* __restrict__ C) {
    __shared__ __align__(16) __half As[128 * 24];
    __shared__ __align__(16) __half Bs[128 * 24];
    int tid = threadIdx.x;
    int w = tid >> 5, lane = tid & 31;
    int g = lane >> 2, t2 = (lane & 3) * 2;
    int wm = w >> 2, wn = w & 3;
    int rb = blockIdx.y * 128, cb = blockIdx.x * 128;

    float acc[16][4];
#pragma unroll
    for (int i = 0; i < 16; i++)
#pragma unroll
        for (int q = 0; q < 4; q++) acc[i][q] = 0.f;

    int r = tid >> 1, p = tid & 1;
#pragma unroll 2
    for (int kc = 0; kc < 24; kc++) {
        *reinterpret_cast<uint4*>(&As[r * 24 + p * 8]) =
            *reinterpret_cast<const uint4*>(&g_xa[(size_t)(rb + r) * 384 + kc * 16 + p * 8]);
        *reinterpret_cast<uint4*>(&Bs[r * 24 + p * 8]) =
            *reinterpret_cast<const uint4*>(&g_xb[(size_t)(cb + r) * 384 + kc * 16 + p * 8]);
        __syncthreads();
        unsigned af[4][4], bf[4][2];
#pragma unroll
        for (int mt = 0; mt < 4; mt++) {
            int mb = wm * 64 + mt * 16;
            af[mt][0] = *reinterpret_cast<const unsigned*>(&As[(mb + g)     * 24 + t2]);
            af[mt][1] = *reinterpret_cast<const unsigned*>(&As[(mb + g + 8) * 24 + t2]);
            af[mt][2] = *reinterpret_cast<const unsigned*>(&As[(mb + g)     * 24 + t2 + 8]);
            af[mt][3] = *reinterpret_cast<const unsigned*>(&As[(mb + g + 8) * 24 + t2 + 8]);
        }
#pragma unroll
        for (int nt = 0; nt < 4; nt++) {
            int nb = wn * 32 + nt * 8;
            bf[nt][0] = *reinterpret_cast<const unsigned*>(&Bs[(nb + g) * 24 + t2]);
            bf[nt][1] = *reinterpret_cast<const unsigned*>(&Bs[(nb + g) * 24 + t2 + 8]);
        }
#pragma unroll
        for (int mt = 0; mt < 4; mt++)
#pragma unroll
            for (int nt = 0; nt < 4; nt++)
                mma16816(acc[mt * 4 + nt], af[mt], bf[nt][0], bf[nt][1]);
        __syncthreads();
    }
#pragma unroll
    for (int mt = 0; mt < 4; mt++) {
#pragma unroll
        for (int nt = 0; nt < 4; nt++) {
            int row = rb + wm * 64 + mt * 16 + g;
            int col = cb + wn * 32 + nt * 8 + t2;
            float2 v0 = make_float2(acc[mt * 4 + nt][0], acc[mt * 4 + nt][1]);
            float2 v1 = make_float2(acc[mt * 4 + nt][2], acc[mt * 4 + nt][3]);
            *reinterpret_cast<float2*>(&C[(size_t)row * NN + col]) = v0;
            *reinterpret_cast<float2*>(&C[(size_t)(row + 8) * NN + col]) = v1;
        }
    }
}

// ---- MLP head ----
__global__ void mlp_kernel(const float* __restrict__ emb,
                           const float* __restrict__ W1, const float* __restrict__ b1,
                           const float* __restrict__ W2, const float* __restrict__ b2,
                           float* __restrict__ mu, float* __restrict__ sigma) {
    int n = blockIdx.x, tid = threadIdx.x;
    __shared__ float se[128], sh[32];
    se[tid] = emb[(size_t)n * HD + tid];
    __syncthreads();
    if (tid < 32) {
        float a = b1[tid];
#pragma unroll 8
        for (int k = 0; k < 128; k++) a += se[k] * W1[k * 32 + tid];
        sh[tid] = a > 0.f ? a : 0.f;
    }
    __syncthreads();
    if (tid < 2) {
        float a = b2[tid];
#pragma unroll
        for (int k = 0; k < 32; k++) a += sh[k] * W2[k * 2 + tid];
        if (tid == 0) mu[n] = a; else sigma[n] = a;
    }
}

extern "C" void kernel_launch(void* const* d_in, const int* in_sizes, int n_in,
                              void* d_out, int out_size) {
    const float* x       = (const float*)d_in[0];
    const int*   ei      = (const int*)  d_in[1];
    const float* W_gat   = (const float*)d_in[2];
    const float* att_src = (const float*)d_in[3];
    const float* att_dst = (const float*)d_in[4];
    const float* b_gat   = (const float*)d_in[5];
    const float* W_ih    = (const float*)d_in[6];
    const float* W_hh    = (const float*)d_in[7];
    const float* b_ih    = (const float*)d_in[8];
    const float* b_hh    = (const float*)d_in[9];
    const float* W1      = (const float*)d_in[10];
    const float* b1      = (const float*)d_in[11];
    const float* W2      = (const float*)d_in[12];
    const float* b2      = (const float*)d_in[13];
    float* out = (float*)d_out;

    float* emb   = out;
    float* corr  = out + (size_t)NN * HD;
    float* mu    = corr + (size_t)NN * NN;
    float* sigma = mu + NN;

    void *p_h, *p_g, *p_xg;
    cudaGetSymbolAddress(&p_h,  g_h);
    cudaGetSymbolAddress(&p_g,  g_g);
    cudaGetSymbolAddress(&p_xg, g_xg);

    zero_cnt_kernel<<<(NN + 255) / 256, 256>>>();

    gemm_kernel<false, false><<<dim3(512 / 64, NN / 64), 256>>>(
        x, W_gat, nullptr, nullptr, (float*)p_h, NN, 512, DIN);

    a_kernel<<<NN, 512>>>(att_src, att_dst);

    count_kernel<<<(NE + 255) / 256, 256>>>(ei);
    scan_kernel<<<1, 1024>>>();
    scatter_kernel<<<(NE + 255) / 256, 256>>>(ei);

    gat_agg_kernel<<<NN, 512>>>(b_gat);

    gemm_kernel<true, true><<<dim3(512 / 64, NN / 64), 256>>>(
        (const float*)p_g, W_ih, b_ih, b_hh, (float*)p_xg, NN, 512, HD);

    lstm_kernel<<<1, 512>>>(W_hh, emb);

    xn_pack_kernel<<<NN, 128>>>(emb);

    corr_kernel<<<dim3(NN / 128, NN / 128), 256>>>(corr);

    mlp_kernel<<<NN, 128>>>(emb, W1, b1, W2, b2, mu, sigma);
}

// round 7
// speedup vs baseline: 1.1674x; 1.1674x over previous
#include <cuda_runtime.h>
#include <cuda_fp16.h>
#include <cstdint>

#define NN   4096
#define DIN  128
#define HD   128
#define NE   131072
#define TOTE (NE + NN)
#define NEG  0.2f
#define G4   512

__device__ float g_h[NN * 512];
__device__ float g_asrc[NN * 4];
__device__ float g_adst[NN * 4];
__device__ int   g_cnt[NN];
__device__ int   g_off[NN + 1];
__device__ int   g_cur[NN];
__device__ int   g_srcs[TOTE];
__device__ float g_g[NN * HD];
__device__ float g_xg[(NN + 1) * G4];   // [t][4*unit+gate], +1 row slack for prefetch
__device__ __half g_xa[NN * 384];
__device__ __half g_xb[NN * 384];

__device__ __forceinline__ unsigned pack_h2(float x, float y) {
    __half2 h = __floats2half2_rn(x, y);
    return *reinterpret_cast<unsigned*>(&h);
}

__device__ __forceinline__ void mma16816(float* d, const unsigned* a, unsigned b0, unsigned b1) {
    asm volatile(
        "mma.sync.aligned.m16n8k16.row.col.f32.f16.f16.f32 "
        "{%0,%1,%2,%3}, {%4,%5,%6,%7}, {%8,%9}, {%0,%1,%2,%3};\n"
        : "+f"(d[0]), "+f"(d[1]), "+f"(d[2]), "+f"(d[3])
        : "r"(a[0]), "r"(a[1]), "r"(a[2]), "r"(a[3]), "r"(b0), "r"(b1));
}

__device__ __forceinline__ void ldsm4(unsigned& r0, unsigned& r1, unsigned& r2, unsigned& r3,
                                      uint32_t addr) {
    asm volatile("ldmatrix.sync.aligned.m8n8.x4.shared.b16 {%0,%1,%2,%3}, [%4];"
        : "=r"(r0), "=r"(r1), "=r"(r2), "=r"(r3) : "r"(addr));
}

__global__ void zero_cnt_kernel() {
    int i = blockIdx.x * blockDim.x + threadIdx.x;
    if (i < NN) g_cnt[i] = 0;
}

// ---- generic tiled SGEMM: C = A(MxK) @ B (+bias +bias2); PERM packs LSTM gate layout ----
template <bool TRANSB, bool PERM>
__global__ __launch_bounds__(256)
void gemm_kernel(const float* __restrict__ A, const float* __restrict__ B,
                 const float* __restrict__ bias, const float* __restrict__ bias2,
                 float* __restrict__ C, int M, int N, int K) {
    const int BK = 16;
    __shared__ float As[64][BK + 1];
    __shared__ float Bs[BK][64 + 1];
    int tid = threadIdx.x;
    int tx = tid & 15, ty = tid >> 4;
    int row0 = blockIdx.y * 64, col0 = blockIdx.x * 64;
    float acc[4][4];
#pragma unroll
    for (int r = 0; r < 4; r++)
#pragma unroll
        for (int c = 0; c < 4; c++) acc[r][c] = 0.f;

    for (int k0 = 0; k0 < K; k0 += BK) {
#pragma unroll
        for (int l = 0; l < 4; l++) {
            int idx = tid + l * 256;
            int m = idx >> 4, k = idx & 15;
            As[m][k] = A[(size_t)(row0 + m) * K + (k0 + k)];
        }
#pragma unroll
        for (int l = 0; l < 4; l++) {
            int idx = tid + l * 256;
            if (!TRANSB) {
                int k = idx >> 6, nn = idx & 63;
                Bs[k][nn] = (col0 + nn < N) ? B[(size_t)(k0 + k) * N + (col0 + nn)] : 0.f;
            } else {
                int nn = idx >> 4, k = idx & 15;
                Bs[k][nn] = (col0 + nn < N) ? B[(size_t)(col0 + nn) * K + (k0 + k)] : 0.f;
            }
        }
        __syncthreads();
#pragma unroll
        for (int k = 0; k < BK; k++) {
            float a[4], b[4];
#pragma unroll
            for (int r = 0; r < 4; r++) a[r] = As[ty * 4 + r][k];
#pragma unroll
            for (int c = 0; c < 4; c++) b[c] = Bs[k][tx * 4 + c];
#pragma unroll
            for (int r = 0; r < 4; r++)
#pragma unroll
                for (int c = 0; c < 4; c++) acc[r][c] += a[r] * b[c];
        }
        __syncthreads();
    }
#pragma unroll
    for (int r = 0; r < 4; r++) {
        int row = row0 + ty * 4 + r;
#pragma unroll
        for (int c = 0; c < 4; c++) {
            int col = col0 + tx * 4 + c;
            if (col < N) {
                float v = acc[r][c];
                if (bias)  v += bias[col];
                if (bias2) v += bias2[col];
                int oc = PERM ? ((col & 127) * 4 + (col >> 7)) : col;
                C[(size_t)row * N + oc] = v;
            }
        }
    }
}

// ---- attention logits ----
__global__ void a_kernel(const float* __restrict__ att_src,
                         const float* __restrict__ att_dst) {
    int n = blockIdx.x, tid = threadIdx.x;
    float hv = g_h[(size_t)n * 512 + tid];
    float ps = hv * att_src[tid];
    float pd = hv * att_dst[tid];
#pragma unroll
    for (int o = 16; o > 0; o >>= 1) {
        ps += __shfl_down_sync(0xffffffffu, ps, o);
        pd += __shfl_down_sync(0xffffffffu, pd, o);
    }
    __shared__ float sps[16], spd[16];
    int w = tid >> 5;
    if ((tid & 31) == 0) { sps[w] = ps; spd[w] = pd; }
    __syncthreads();
    if (tid < 4) {
        g_asrc[n * 4 + tid] = sps[tid * 4] + sps[tid * 4 + 1] + sps[tid * 4 + 2] + sps[tid * 4 + 3];
        g_adst[n * 4 + tid] = spd[tid * 4] + spd[tid * 4 + 1] + spd[tid * 4 + 2] + spd[tid * 4 + 3];
    }
}

__global__ void count_kernel(const int* __restrict__ ei) {
    int i = blockIdx.x * blockDim.x + threadIdx.x;
    if (i < NE) atomicAdd(&g_cnt[ei[NE + i]], 1);
    if (i < NN) atomicAdd(&g_cnt[i], 1);
}

__global__ void scan_kernel() {
    __shared__ int s[1024];
    int tid = threadIdx.x;
    int c[4]; int sum = 0;
#pragma unroll
    for (int i = 0; i < 4; i++) { c[i] = g_cnt[tid * 4 + i]; sum += c[i]; }
    s[tid] = sum;
    __syncthreads();
    for (int off = 1; off < 1024; off <<= 1) {
        int v = s[tid];
        int add = (tid >= off) ? s[tid - off] : 0;
        __syncthreads();
        s[tid] = v + add;
        __syncthreads();
    }
    int run = (tid == 0) ? 0 : s[tid - 1];
#pragma unroll
    for (int i = 0; i < 4; i++) {
        g_off[tid * 4 + i] = run;
        g_cur[tid * 4 + i] = run;
        run += c[i];
    }
    if (tid == 1023) g_off[NN] = run;
}

__global__ void scatter_kernel(const int* __restrict__ ei) {
    int i = blockIdx.x * blockDim.x + threadIdx.x;
    if (i < NE) {
        int d = ei[NE + i];
        g_srcs[atomicAdd(&g_cur[d], 1)] = ei[i];
    }
    if (i < NN) g_srcs[atomicAdd(&g_cur[i], 1)] = i;
}

// ---- GAT softmax + aggregate ----
#define CHUNK 512
__global__ __launch_bounds__(512)
void gat_agg_kernel(const float* __restrict__ b_gat) {
    int n = blockIdx.x, tid = threadIdx.x;
    int beg = g_off[n], end = g_off[n + 1];
    int deg = end - beg;

    __shared__ int   ssrc[CHUNK];
    __shared__ float salpha[CHUNK * 4];
    __shared__ float red[512];
    __shared__ float m_sh[4], rs_sh[4];

    int hh = tid & 3;
    float adst = g_adst[n * 4 + hh];
    float mx = -1e30f;
    for (int e = tid >> 2; e < deg; e += 128) {
        int s = g_srcs[beg + e];
        float v = g_asrc[s * 4 + hh] + adst;
        v = v >= 0.f ? v : NEG * v;
        mx = fmaxf(mx, v);
    }
    red[tid] = mx;
    __syncthreads();
    for (int s = 256; s >= 4; s >>= 1) {
        if (tid < s) red[tid] = fmaxf(red[tid], red[tid + s]);
        __syncthreads();
    }
    if (tid < 4) m_sh[tid] = red[tid];
    __syncthreads();

    float m = m_sh[hh];
    float ssum = 0.f;
    for (int e = tid >> 2; e < deg; e += 128) {
        int s = g_srcs[beg + e];
        float v = g_asrc[s * 4 + hh] + adst;
        v = v >= 0.f ? v : NEG * v;
        ssum += __expf(v - m);
    }
    __syncthreads();
    red[tid] = ssum;
    __syncthreads();
    for (int s = 256; s >= 4; s >>= 1) {
        if (tid < s) red[tid] += red[tid + s];
        __syncthreads();
    }
    if (tid < 4) rs_sh[tid] = 1.0f / (red[tid] + 1e-16f);
    __syncthreads();

    int head = tid >> 7;
    float acc = 0.f;
    float4 ad4 = *reinterpret_cast<const float4*>(&g_adst[n * 4]);
    float m0 = m_sh[0], m1 = m_sh[1], m2 = m_sh[2], m3 = m_sh[3];
    float r0 = rs_sh[0], r1 = rs_sh[1], r2 = rs_sh[2], r3 = rs_sh[3];

    for (int base = 0; base < deg; base += CHUNK) {
        int cnt = min(CHUNK, deg - base);
        __syncthreads();
        if (tid < cnt) {
            int s = g_srcs[beg + base + tid];
            ssrc[tid] = s;
            float4 as4 = *reinterpret_cast<const float4*>(&g_asrc[s * 4]);
            float e0 = as4.x + ad4.x; e0 = e0 >= 0.f ? e0 : NEG * e0;
            float e1 = as4.y + ad4.y; e1 = e1 >= 0.f ? e1 : NEG * e1;
            float e2 = as4.z + ad4.z; e2 = e2 >= 0.f ? e2 : NEG * e2;
            float e3 = as4.w + ad4.w; e3 = e3 >= 0.f ? e3 : NEG * e3;
            salpha[tid * 4 + 0] = __expf(e0 - m0) * r0;
            salpha[tid * 4 + 1] = __expf(e1 - m1) * r1;
            salpha[tid * 4 + 2] = __expf(e2 - m2) * r2;
            salpha[tid * 4 + 3] = __expf(e3 - m3) * r3;
        }
        __syncthreads();
#pragma unroll 4
        for (int e = 0; e < cnt; e++)
            acc += salpha[e * 4 + head] * g_h[(size_t)ssrc[e] * 512 + tid];
    }
    __syncthreads();
    red[tid] = acc;
    __syncthreads();
    if (tid < HD) {
        float s = red[tid] + red[128 + tid] + red[256 + tid] + red[384 + tid];
        float gv = s * 0.25f + b_gat[tid];
        g_g[(size_t)n * HD + tid] = gv > 0.f ? gv : 0.f;
    }
}

// ---- LSTM: pure HMMA, ldmatrix b-fragments, 4x4-deep chains, gate-interleaved ----
// Warp w owns permuted rows [32w, 32w+32); W''[R] = W_hh[(R&3)*128 + (R>>2)].
// B is a broadcast vector: all 8 row-addresses of each 8x8 ldmatrix tile point at
// the SAME 16B of h, so lane l receives {h[k0+t2], h[k0+t2+1]} = the exact mma
// B-fragment. 4 LDSM/warp replace 16 LDS.32.
__global__ __launch_bounds__(512, 1)
void lstm_kernel(const float* __restrict__ Whh, float* __restrict__ emb_out) {
    __shared__ __align__(16) __half hsh[128];
    __shared__ __align__(16) float gact[512];
    int tid = threadIdx.x;
    int w = tid >> 5, lane = tid & 31;
    int grp = lane >> 2, t2 = (lane & 3) * 2;
    int gate = lane & 3;

    // A fragments for all 8 k-chunks (gate-interleaved permuted rows)
    unsigned a[2][8][4];
#pragma unroll
    for (int mt = 0; mt < 2; mt++) {
        int rb = w * 32 + mt * 16;
#pragma unroll
        for (int kc = 0; kc < 8; kc++) {
            int cb = kc * 16;
            int r0 = rb + grp, r1 = rb + grp + 8;
            const float* row0 = Whh + (size_t)((r0 & 3) * 128 + (r0 >> 2)) * 128;
            const float* row1 = Whh + (size_t)((r1 & 3) * 128 + (r1 >> 2)) * 128;
            a[mt][kc][0] = pack_h2(row0[cb + t2],     row0[cb + t2 + 1]);
            a[mt][kc][1] = pack_h2(row1[cb + t2],     row1[cb + t2 + 1]);
            a[mt][kc][2] = pack_h2(row0[cb + t2 + 8], row0[cb + t2 + 9]);
            a[mt][kc][3] = pack_h2(row1[cb + t2 + 8], row1[cb + t2 + 9]);
        }
    }
    if (tid < 64) reinterpret_cast<__half2*>(hsh)[tid] = __floats2half2_rn(0.f, 0.f);
    float c = 0.f;
    __syncthreads();

    // ldmatrix lane addresses (fixed): ldsm q covers kc=2q,2q+1;
    // matrix m (lane group l>>3) reads the 16B at h + 64q + 16*m
    uint32_t hbase = (uint32_t)__cvta_generic_to_shared(hsh);
    uint32_t lmoff = hbase + (uint32_t)((lane >> 3) << 4);

    float xg = g_xg[tid];
#pragma unroll 1
    for (int t = 0; t < NN; t++) {
        float d0a[4] = {0.f, 0.f, 0.f, 0.f};
        float d1a[4] = {0.f, 0.f, 0.f, 0.f};
        float d0b[4] = {0.f, 0.f, 0.f, 0.f};
        float d1b[4] = {0.f, 0.f, 0.f, 0.f};
        {
            unsigned b0, b1, b2, b3, b4, b5, b6, b7;
            ldsm4(b0, b1, b2, b3, lmoff);            // kc0 (b0,b1), kc1 (b2,b3)
            ldsm4(b4, b5, b6, b7, lmoff + 64);       // kc2, kc3
            mma16816(d0a, a[0][0], b0, b1);
            mma16816(d1a, a[1][0], b0, b1);
            mma16816(d0a, a[0][1], b2, b3);
            mma16816(d1a, a[1][1], b2, b3);
            mma16816(d0a, a[0][2], b4, b5);
            mma16816(d1a, a[1][2], b4, b5);
            mma16816(d0a, a[0][3], b6, b7);
            mma16816(d1a, a[1][3], b6, b7);
        }
        {
            unsigned b0, b1, b2, b3, b4, b5, b6, b7;
            ldsm4(b0, b1, b2, b3, lmoff + 128);      // kc4, kc5
            ldsm4(b4, b5, b6, b7, lmoff + 192);      // kc6, kc7
            mma16816(d0b, a[0][4], b0, b1);
            mma16816(d1b, a[1][4], b0, b1);
            mma16816(d0b, a[0][5], b2, b3);
            mma16816(d1b, a[1][5], b2, b3);
            mma16816(d0b, a[0][6], b4, b5);
            mma16816(d1b, a[1][6], b4, b5);
            mma16816(d0b, a[0][7], b6, b7);
            mma16816(d1b, a[1][7], b6, b7);
        }
        float xgn = g_xg[(size_t)(t + 1) * 512 + tid];
        float e0 = d0a[0] + d0b[0];
        float e2 = d0a[2] + d0b[2];
        float f0 = d1a[0] + d1b[0];
        float f2 = d1a[2] + d1b[2];
        // select column 0 so lane l holds its permuted row's partial
        int src = (lane & 7) * 4;
        float s00 = __shfl_sync(0xffffffffu, e0, src);
        float s02 = __shfl_sync(0xffffffffu, e2, src);
        float s10 = __shfl_sync(0xffffffffu, f0, src);
        float s12 = __shfl_sync(0xffffffffu, f2, src);
        float v = (lane & 16) ? ((lane & 8) ? s12 : s10) : ((lane & 8) ? s02 : s00);
        float z = v + xg;
        float act;
        if (gate == 2) act = __fdividef(2.f, 1.f + __expf(-2.f * z)) - 1.f;
        else           act = __fdividef(1.f, 1.f + __expf(-z));
        gact[tid] = act;
        __syncthreads();
        if (tid < 128) {
            float4 g4 = *reinterpret_cast<const float4*>(&gact[tid * 4]);
            c = g4.y * c + g4.x * g4.z;
            float th = __fdividef(2.f, 1.f + __expf(-2.f * c)) - 1.f;
            float hn = g4.w * th;
            emb_out[(size_t)t * HD + tid] = hn;
            hsh[tid] = __float2half_rn(hn);
        }
        __syncthreads();
        xg = xgn;
    }
}

// ---- normalize + pack split-fp16 for corr ----
__global__ void xn_pack_kernel(const float* __restrict__ emb) {
    int n = blockIdx.x, tid = threadIdx.x;
    float v = emb[(size_t)n * HD + tid];
    float ss = v * v;
#pragma unroll
    for (int o = 16; o > 0; o >>= 1) ss += __shfl_down_sync(0xffffffffu, ss, o);
    __shared__ float sw[4];
    __shared__ float rsh;
    if ((tid & 31) == 0) sw[tid >> 5] = ss;
    __syncthreads();
    if (tid == 0) rsh = 1.0f / fmaxf(sqrtf(sw[0] + sw[1] + sw[2] + sw[3]), 1e-12f);
    __syncthreads();
    float xv = v * rsh;
    __half hi = __float2half_rn(xv);
    __half lo = __float2half_rn(xv - __half2float(hi));
    size_t base = (size_t)n * 384;
    g_xa[base + tid]       = hi;
    g_xa[base + 128 + tid] = lo;
    g_xa[base + 256 + tid] = hi;
    g_xb[base + tid]       = hi;
    g_xb[base + 128 + tid] = hi;
    g_xb[base + 256 + tid] = lo;
}

// ---- corr = xa @ xb^T via HMMA, K=384 (split-fp16 exact) ----
__global__ __launch_bounds__(256, 2)
void corr_kernel(float* __restrict__ C) {
    __shared__ __align__(16) __half As[128 * 24];
    __shared__ __align__(16) __half Bs[128 * 24];
    int tid = threadIdx.x;
    int w = tid >> 5, lane = tid & 31;
    int g = lane >> 2, t2 = (lane & 3) * 2;
    int wm = w >> 2, wn = w & 3;
    int rb = blockIdx.y * 128, cb = blockIdx.x * 128;

    float acc[16][4];
#pragma unroll
    for (int i = 0; i < 16; i++)
#pragma unroll
        for (int q = 0; q < 4; q++) acc[i][q] = 0.f;

    int r = tid >> 1, p = tid & 1;
#pragma unroll 2
    for (int kc = 0; kc < 24; kc++) {
        *reinterpret_cast<uint4*>(&As[r * 24 + p * 8]) =
            *reinterpret_cast<const uint4*>(&g_xa[(size_t)(rb + r) * 384 + kc * 16 + p * 8]);
        *reinterpret_cast<uint4*>(&Bs[r * 24 + p * 8]) =
            *reinterpret_cast<const uint4*>(&g_xb[(size_t)(cb + r) * 384 + kc * 16 + p * 8]);
        __syncthreads();
        unsigned af[4][4], bf[4][2];
#pragma unroll
        for (int mt = 0; mt < 4; mt++) {
            int mb = wm * 64 + mt * 16;
            af[mt][0] = *reinterpret_cast<const unsigned*>(&As[(mb + g)     * 24 + t2]);
            af[mt][1] = *reinterpret_cast<const unsigned*>(&As[(mb + g + 8) * 24 + t2]);
            af[mt][2] = *reinterpret_cast<const unsigned*>(&As[(mb + g)     * 24 + t2 + 8]);
            af[mt][3] = *reinterpret_cast<const unsigned*>(&As[(mb + g + 8) * 24 + t2 + 8]);
        }
#pragma unroll
        for (int nt = 0; nt < 4; nt++) {
            int nb = wn * 32 + nt * 8;
            bf[nt][0] = *reinterpret_cast<const unsigned*>(&Bs[(nb + g) * 24 + t2]);
            bf[nt][1] = *reinterpret_cast<const unsigned*>(&Bs[(nb + g) * 24 + t2 + 8]);
        }
#pragma unroll
        for (int mt = 0; mt < 4; mt++)
#pragma unroll
            for (int nt = 0; nt < 4; nt++)
                mma16816(acc[mt * 4 + nt], af[mt], bf[nt][0], bf[nt][1]);
        __syncthreads();
    }
#pragma unroll
    for (int mt = 0; mt < 4; mt++) {
#pragma unroll
        for (int nt = 0; nt < 4; nt++) {
            int row = rb + wm * 64 + mt * 16 + g;
            int col = cb + wn * 32 + nt * 8 + t2;
            float2 v0 = make_float2(acc[mt * 4 + nt][0], acc[mt * 4 + nt][1]);
            float2 v1 = make_float2(acc[mt * 4 + nt][2], acc[mt * 4 + nt][3]);
            *reinterpret_cast<float2*>(&C[(size_t)row * NN + col]) = v0;
            *reinterpret_cast<float2*>(&C[(size_t)(row + 8) * NN + col]) = v1;
        }
    }
}

// ---- MLP head ----
__global__ void mlp_kernel(const float* __restrict__ emb,
                           const float* __restrict__ W1, const float* __restrict__ b1,
                           const float* __restrict__ W2, const float* __restrict__ b2,
                           float* __restrict__ mu, float* __restrict__ sigma) {
    int n = blockIdx.x, tid = threadIdx.x;
    __shared__ float se[128], sh[32];
    se[tid] = emb[(size_t)n * HD + tid];
    __syncthreads();
    if (tid < 32) {
        float a = b1[tid];
#pragma unroll 8
        for (int k = 0; k < 128; k++) a += se[k] * W1[k * 32 + tid];
        sh[tid] = a > 0.f ? a : 0.f;
    }
    __syncthreads();
    if (tid < 2) {
        float a = b2[tid];
#pragma unroll
        for (int k = 0; k < 32; k++) a += sh[k] * W2[k * 2 + tid];
        if (tid == 0) mu[n] = a; else sigma[n] = a;
    }
}

extern "C" void kernel_launch(void* const* d_in, const int* in_sizes, int n_in,
                              void* d_out, int out_size) {
    const float* x       = (const float*)d_in[0];
    const int*   ei      = (const int*)  d_in[1];
    const float* W_gat   = (const float*)d_in[2];
    const float* att_src = (const float*)d_in[3];
    const float* att_dst = (const float*)d_in[4];
    const float* b_gat   = (const float*)d_in[5];
    const float* W_ih    = (const float*)d_in[6];
    const float* W_hh    = (const float*)d_in[7];
    const float* b_ih    = (const float*)d_in[8];
    const float* b_hh    = (const float*)d_in[9];
    const float* W1      = (const float*)d_in[10];
    const float* b1      = (const float*)d_in[11];
    const float* W2      = (const float*)d_in[12];
    const float* b2      = (const float*)d_in[13];
    float* out = (float*)d_out;

    float* emb   = out;
    float* corr  = out + (size_t)NN * HD;
    float* mu    = corr + (size_t)NN * NN;
    float* sigma = mu + NN;

    void *p_h, *p_g, *p_xg;
    cudaGetSymbolAddress(&p_h,  g_h);
    cudaGetSymbolAddress(&p_g,  g_g);
    cudaGetSymbolAddress(&p_xg, g_xg);

    zero_cnt_kernel<<<(NN + 255) / 256, 256>>>();

    gemm_kernel<false, false><<<dim3(512 / 64, NN / 64), 256>>>(
        x, W_gat, nullptr, nullptr, (float*)p_h, NN, 512, DIN);

    a_kernel<<<NN, 512>>>(att_src, att_dst);

    count_kernel<<<(NE + 255) / 256, 256>>>(ei);
    scan_kernel<<<1, 1024>>>();
    scatter_kernel<<<(NE + 255) / 256, 256>>>(ei);

    gat_agg_kernel<<<NN, 512>>>(b_gat);

    gemm_kernel<true, true><<<dim3(512 / 64, NN / 64), 256>>>(
        (const float*)p_g, W_ih, b_ih, b_hh, (float*)p_xg, NN, 512, HD);

    lstm_kernel<<<1, 512>>>(W_hh, emb);

    xn_pack_kernel<<<NN, 128>>>(emb);

    corr_kernel<<<dim3(NN / 128, NN / 128), 256>>>(corr);

    mlp_kernel<<<NN, 128>>>(emb, W1, b1, W2, b2, mu, sigma);
}

// round 8
// speedup vs baseline: 1.2091x; 1.0357x over previous
#include <cuda_runtime.h>
#include <cuda_fp16.h>
#include <cstdint>

#define NN   4096
#define DIN  128
#define HD   128
#define NE   131072
#define TOTE (NE + NN)
#define NEG  0.2f
#define G4   512

__device__ float g_h[NN * 512];
__device__ float g_asrc[NN * 4];
__device__ float g_adst[NN * 4];
__device__ int   g_cnt[NN];
__device__ int   g_off[NN + 1];
__device__ int   g_cur[NN];
__device__ int   g_srcs[TOTE];
__device__ float g_g[NN * HD];
__device__ float g_xg[(NN + 1) * G4];   // [t][j], j = gate*128+unit; +1 row slack
__device__ __half g_xa[NN * 384];
__device__ __half g_xb[NN * 384];

__device__ __forceinline__ unsigned pack_h2(float x, float y) {
    __half2 h = __floats2half2_rn(x, y);
    return *reinterpret_cast<unsigned*>(&h);
}

__device__ __forceinline__ void mma16816(float* d, const unsigned* a, unsigned b0, unsigned b1) {
    asm volatile(
        "mma.sync.aligned.m16n8k16.row.col.f32.f16.f16.f32 "
        "{%0,%1,%2,%3}, {%4,%5,%6,%7}, {%8,%9}, {%0,%1,%2,%3};\n"
        : "+f"(d[0]), "+f"(d[1]), "+f"(d[2]), "+f"(d[3])
        : "r"(a[0]), "r"(a[1]), "r"(a[2]), "r"(a[3]), "r"(b0), "r"(b1));
}

__global__ void zero_cnt_kernel() {
    int i = blockIdx.x * blockDim.x + threadIdx.x;
    if (i < NN) g_cnt[i] = 0;
}

// ---- generic tiled SGEMM: C = A(MxK) @ B (+bias +bias2) ----
template <bool TRANSB, bool PERM>
__global__ __launch_bounds__(256)
void gemm_kernel(const float* __restrict__ A, const float* __restrict__ B,
                 const float* __restrict__ bias, const float* __restrict__ bias2,
                 float* __restrict__ C, int M, int N, int K) {
    const int BK = 16;
    __shared__ float As[64][BK + 1];
    __shared__ float Bs[BK][64 + 1];
    int tid = threadIdx.x;
    int tx = tid & 15, ty = tid >> 4;
    int row0 = blockIdx.y * 64, col0 = blockIdx.x * 64;
    float acc[4][4];
#pragma unroll
    for (int r = 0; r < 4; r++)
#pragma unroll
        for (int c = 0; c < 4; c++) acc[r][c] = 0.f;

    for (int k0 = 0; k0 < K; k0 += BK) {
#pragma unroll
        for (int l = 0; l < 4; l++) {
            int idx = tid + l * 256;
            int m = idx >> 4, k = idx & 15;
            As[m][k] = A[(size_t)(row0 + m) * K + (k0 + k)];
        }
#pragma unroll
        for (int l = 0; l < 4; l++) {
            int idx = tid + l * 256;
            if (!TRANSB) {
                int k = idx >> 6, nn = idx & 63;
                Bs[k][nn] = (col0 + nn < N) ? B[(size_t)(k0 + k) * N + (col0 + nn)] : 0.f;
            } else {
                int nn = idx >> 4, k = idx & 15;
                Bs[k][nn] = (col0 + nn < N) ? B[(size_t)(col0 + nn) * K + (k0 + k)] : 0.f;
            }
        }
        __syncthreads();
#pragma unroll
        for (int k = 0; k < BK; k++) {
            float a[4], b[4];
#pragma unroll
            for (int r = 0; r < 4; r++) a[r] = As[ty * 4 + r][k];
#pragma unroll
            for (int c = 0; c < 4; c++) b[c] = Bs[k][tx * 4 + c];
#pragma unroll
            for (int r = 0; r < 4; r++)
#pragma unroll
                for (int c = 0; c < 4; c++) acc[r][c] += a[r] * b[c];
        }
        __syncthreads();
    }
#pragma unroll
    for (int r = 0; r < 4; r++) {
        int row = row0 + ty * 4 + r;
#pragma unroll
        for (int c = 0; c < 4; c++) {
            int col = col0 + tx * 4 + c;
            if (col < N) {
                float v = acc[r][c];
                if (bias)  v += bias[col];
                if (bias2) v += bias2[col];
                int oc = PERM ? ((col & 127) * 4 + (col >> 7)) : col;
                C[(size_t)row * N + oc] = v;
            }
        }
    }
}

// ---- attention logits ----
__global__ void a_kernel(const float* __restrict__ att_src,
                         const float* __restrict__ att_dst) {
    int n = blockIdx.x, tid = threadIdx.x;
    float hv = g_h[(size_t)n * 512 + tid];
    float ps = hv * att_src[tid];
    float pd = hv * att_dst[tid];
#pragma unroll
    for (int o = 16; o > 0; o >>= 1) {
        ps += __shfl_down_sync(0xffffffffu, ps, o);
        pd += __shfl_down_sync(0xffffffffu, pd, o);
    }
    __shared__ float sps[16], spd[16];
    int w = tid >> 5;
    if ((tid & 31) == 0) { sps[w] = ps; spd[w] = pd; }
    __syncthreads();
    if (tid < 4) {
        g_asrc[n * 4 + tid] = sps[tid * 4] + sps[tid * 4 + 1] + sps[tid * 4 + 2] + sps[tid * 4 + 3];
        g_adst[n * 4 + tid] = spd[tid * 4] + spd[tid * 4 + 1] + spd[tid * 4 + 2] + spd[tid * 4 + 3];
    }
}

__global__ void count_kernel(const int* __restrict__ ei) {
    int i = blockIdx.x * blockDim.x + threadIdx.x;
    if (i < NE) atomicAdd(&g_cnt[ei[NE + i]], 1);
    if (i < NN) atomicAdd(&g_cnt[i], 1);
}

__global__ void scan_kernel() {
    __shared__ int s[1024];
    int tid = threadIdx.x;
    int c[4]; int sum = 0;
#pragma unroll
    for (int i = 0; i < 4; i++) { c[i] = g_cnt[tid * 4 + i]; sum += c[i]; }
    s[tid] = sum;
    __syncthreads();
    for (int off = 1; off < 1024; off <<= 1) {
        int v = s[tid];
        int add = (tid >= off) ? s[tid - off] : 0;
        __syncthreads();
        s[tid] = v + add;
        __syncthreads();
    }
    int run = (tid == 0) ? 0 : s[tid - 1];
#pragma unroll
    for (int i = 0; i < 4; i++) {
        g_off[tid * 4 + i] = run;
        g_cur[tid * 4 + i] = run;
        run += c[i];
    }
    if (tid == 1023) g_off[NN] = run;
}

__global__ void scatter_kernel(const int* __restrict__ ei) {
    int i = blockIdx.x * blockDim.x + threadIdx.x;
    if (i < NE) {
        int d = ei[NE + i];
        g_srcs[atomicAdd(&g_cur[d], 1)] = ei[i];
    }
    if (i < NN) g_srcs[atomicAdd(&g_cur[i], 1)] = i;
}

// ---- GAT softmax + aggregate ----
#define CHUNK 512
__global__ __launch_bounds__(512)
void gat_agg_kernel(const float* __restrict__ b_gat) {
    int n = blockIdx.x, tid = threadIdx.x;
    int beg = g_off[n], end = g_off[n + 1];
    int deg = end - beg;

    __shared__ int   ssrc[CHUNK];
    __shared__ float salpha[CHUNK * 4];
    __shared__ float red[512];
    __shared__ float m_sh[4], rs_sh[4];

    int hh = tid & 3;
    float adst = g_adst[n * 4 + hh];
    float mx = -1e30f;
    for (int e = tid >> 2; e < deg; e += 128) {
        int s = g_srcs[beg + e];
        float v = g_asrc[s * 4 + hh] + adst;
        v = v >= 0.f ? v : NEG * v;
        mx = fmaxf(mx, v);
    }
    red[tid] = mx;
    __syncthreads();
    for (int s = 256; s >= 4; s >>= 1) {
        if (tid < s) red[tid] = fmaxf(red[tid], red[tid + s]);
        __syncthreads();
    }
    if (tid < 4) m_sh[tid] = red[tid];
    __syncthreads();

    float m = m_sh[hh];
    float ssum = 0.f;
    for (int e = tid >> 2; e < deg; e += 128) {
        int s = g_srcs[beg + e];
        float v = g_asrc[s * 4 + hh] + adst;
        v = v >= 0.f ? v : NEG * v;
        ssum += __expf(v - m);
    }
    __syncthreads();
    red[tid] = ssum;
    __syncthreads();
    for (int s = 256; s >= 4; s >>= 1) {
        if (tid < s) red[tid] += red[tid + s];
        __syncthreads();
    }
    if (tid < 4) rs_sh[tid] = 1.0f / (red[tid] + 1e-16f);
    __syncthreads();

    int head = tid >> 7;
    float acc = 0.f;
    float4 ad4 = *reinterpret_cast<const float4*>(&g_adst[n * 4]);
    float m0 = m_sh[0], m1 = m_sh[1], m2 = m_sh[2], m3 = m_sh[3];
    float r0 = rs_sh[0], r1 = rs_sh[1], r2 = rs_sh[2], r3 = rs_sh[3];

    for (int base = 0; base < deg; base += CHUNK) {
        int cnt = min(CHUNK, deg - base);
        __syncthreads();
        if (tid < cnt) {
            int s = g_srcs[beg + base + tid];
            ssrc[tid] = s;
            float4 as4 = *reinterpret_cast<const float4*>(&g_asrc[s * 4]);
            float e0 = as4.x + ad4.x; e0 = e0 >= 0.f ? e0 : NEG * e0;
            float e1 = as4.y + ad4.y; e1 = e1 >= 0.f ? e1 : NEG * e1;
            float e2 = as4.z + ad4.z; e2 = e2 >= 0.f ? e2 : NEG * e2;
            float e3 = as4.w + ad4.w; e3 = e3 >= 0.f ? e3 : NEG * e3;
            salpha[tid * 4 + 0] = __expf(e0 - m0) * r0;
            salpha[tid * 4 + 1] = __expf(e1 - m1) * r1;
            salpha[tid * 4 + 2] = __expf(e2 - m2) * r2;
            salpha[tid * 4 + 3] = __expf(e3 - m3) * r3;
        }
        __syncthreads();
#pragma unroll 4
        for (int e = 0; e < cnt; e++)
            acc += salpha[e * 4 + head] * g_h[(size_t)ssrc[e] * 512 + tid];
    }
    __syncthreads();
    red[tid] = acc;
    __syncthreads();
    if (tid < HD) {
        float s = red[tid] + red[128 + tid] + red[256 + tid] + red[384 + tid];
        float gv = s * 0.25f + b_gat[tid];
        g_g[(size_t)n * HD + tid] = gv > 0.f ? gv : 0.f;
    }
}

// ---- LSTM: r3 structure (best known), single change: 4x 4-deep mma chains ----
// Warp w owns W_hh rows [32w, 32w+32). Thread j = row j. Epilogue: smem gact,
// j<128 does cell update. 2 barriers/step.
__global__ __launch_bounds__(512, 1)
void lstm_kernel(const float* __restrict__ Whh, float* __restrict__ emb_out) {
    __shared__ __align__(16) __half hsh[128];
    __shared__ float gact[512];
    int j = threadIdx.x;
    int w = j >> 5, lane = j & 31;
    int grp = lane >> 2, t2 = (lane & 3) * 2;
    const bool is_g = (w >= 8 && w < 12);

    // Preload A fragments: warp w owns rows [w*32, w*32+32) of W_hh (512x128)
    unsigned a[2][8][4];
#pragma unroll
    for (int mt = 0; mt < 2; mt++) {
        int rb = w * 32 + mt * 16;
#pragma unroll
        for (int kc = 0; kc < 8; kc++) {
            int cb = kc * 16;
            a[mt][kc][0] = pack_h2(Whh[(size_t)(rb + grp)     * 128 + cb + t2],     Whh[(size_t)(rb + grp)     * 128 + cb + t2 + 1]);
            a[mt][kc][1] = pack_h2(Whh[(size_t)(rb + grp + 8) * 128 + cb + t2],     Whh[(size_t)(rb + grp + 8) * 128 + cb + t2 + 1]);
            a[mt][kc][2] = pack_h2(Whh[(size_t)(rb + grp)     * 128 + cb + t2 + 8], Whh[(size_t)(rb + grp)     * 128 + cb + t2 + 9]);
            a[mt][kc][3] = pack_h2(Whh[(size_t)(rb + grp + 8) * 128 + cb + t2 + 8], Whh[(size_t)(rb + grp + 8) * 128 + cb + t2 + 9]);
        }
    }
    if (j < 64) reinterpret_cast<__half2*>(hsh)[j] = __floats2half2_rn(0.f, 0.f);
    float c = 0.f;
    __syncthreads();

    float xg = g_xg[j];
#pragma unroll 1
    for (int t = 0; t < NN; t++) {
        float xgn = g_xg[(size_t)(t + 1) * 512 + j];   // independent prefetch
        float d0a[4] = {0.f, 0.f, 0.f, 0.f};
        float d1a[4] = {0.f, 0.f, 0.f, 0.f};
        float d0b[4] = {0.f, 0.f, 0.f, 0.f};
        float d1b[4] = {0.f, 0.f, 0.f, 0.f};
#pragma unroll
        for (int kc = 0; kc < 4; kc++) {
            unsigned b0 = *reinterpret_cast<const unsigned*>(&hsh[kc * 16 + t2]);
            unsigned b1 = *reinterpret_cast<const unsigned*>(&hsh[kc * 16 + t2 + 8]);
            mma16816(d0a, a[0][kc], b0, b1);
            mma16816(d1a, a[1][kc], b0, b1);
        }
#pragma unroll
        for (int kc = 4; kc < 8; kc++) {
            unsigned b0 = *reinterpret_cast<const unsigned*>(&hsh[kc * 16 + t2]);
            unsigned b1 = *reinterpret_cast<const unsigned*>(&hsh[kc * 16 + t2 + 8]);
            mma16816(d0b, a[0][kc], b0, b1);
            mma16816(d1b, a[1][kc], b0, b1);
        }
        float e0 = d0a[0] + d0b[0];
        float e2 = d0a[2] + d0b[2];
        float f0 = d1a[0] + d1b[0];
        float f2 = d1a[2] + d1b[2];
        // extract column 0: lane wants row w*32+lane
        int src = (lane & 7) * 4;
        float s00 = __shfl_sync(0xffffffffu, e0, src);
        float s02 = __shfl_sync(0xffffffffu, e2, src);
        float s10 = __shfl_sync(0xffffffffu, f0, src);
        float s12 = __shfl_sync(0xffffffffu, f2, src);
        float v = (lane & 16) ? ((lane & 8) ? s12 : s10) : ((lane & 8) ? s02 : s00);
        float z = v + xg;
        float act;
        if (is_g) act = __fdividef(2.f, 1.f + __expf(-2.f * z)) - 1.f;
        else      act = __fdividef(1.f, 1.f + __expf(-z));
        gact[j] = act;
        __syncthreads();
        if (j < HD) {
            float gi = gact[j], gf = gact[128 + j], gg = gact[256 + j], go = gact[384 + j];
            c = gf * c + gi * gg;
            float th = __fdividef(2.f, 1.f + __expf(-2.f * c)) - 1.f;
            float hn = go * th;
            emb_out[(size_t)t * HD + j] = hn;
            hsh[j] = __float2half_rn(hn);
        }
        __syncthreads();
        xg = xgn;
    }
}

// ---- normalize + pack split-fp16 for corr ----
__global__ void xn_pack_kernel(const float* __restrict__ emb) {
    int n = blockIdx.x, tid = threadIdx.x;
    float v = emb[(size_t)n * HD + tid];
    float ss = v * v;
#pragma unroll
    for (int o = 16; o > 0; o >>= 1) ss += __shfl_down_sync(0xffffffffu, ss, o);
    __shared__ float sw[4];
    __shared__ float rsh;
    if ((tid & 31) == 0) sw[tid >> 5] = ss;
    __syncthreads();
    if (tid == 0) rsh = 1.0f / fmaxf(sqrtf(sw[0] + sw[1] + sw[2] + sw[3]), 1e-12f);
    __syncthreads();
    float xv = v * rsh;
    __half hi = __float2half_rn(xv);
    __half lo = __float2half_rn(xv - __half2float(hi));
    size_t base = (size_t)n * 384;
    g_xa[base + tid]       = hi;
    g_xa[base + 128 + tid] = lo;
    g_xa[base + 256 + tid] = hi;
    g_xb[base + tid]       = hi;
    g_xb[base + 128 + tid] = hi;
    g_xb[base + 256 + tid] = lo;
}

// ---- corr = xa @ xb^T via HMMA, K=384 (split-fp16 exact) ----
__global__ __launch_bounds__(256, 2)
void corr_kernel(float* __restrict__ C) {
    __shared__ __align__(16) __half As[128 * 24];
    __shared__ __align__(16) __half Bs[128 * 24];
    int tid = threadIdx.x;
    int w = tid >> 5, lane = tid & 31;
    int g = lane >> 2, t2 = (lane & 3) * 2;
    int wm = w >> 2, wn = w & 3;
    int rb = blockIdx.y * 128, cb = blockIdx.x * 128;

    float acc[16][4];
#pragma unroll
    for (int i = 0; i < 16; i++)
#pragma unroll
        for (int q = 0; q < 4; q++) acc[i][q] = 0.f;

    int r = tid >> 1, p = tid & 1;
#pragma unroll 2
    for (int kc = 0; kc < 24; kc++) {
        *reinterpret_cast<uint4*>(&As[r * 24 + p * 8]) =
            *reinterpret_cast<const uint4*>(&g_xa[(size_t)(rb + r) * 384 + kc * 16 + p * 8]);
        *reinterpret_cast<uint4*>(&Bs[r * 24 + p * 8]) =
            *reinterpret_cast<const uint4*>(&g_xb[(size_t)(cb + r) * 384 + kc * 16 + p * 8]);
        __syncthreads();
        unsigned af[4][4], bf[4][2];
#pragma unroll
        for (int mt = 0; mt < 4; mt++) {
            int mb = wm * 64 + mt * 16;
            af[mt][0] = *reinterpret_cast<const unsigned*>(&As[(mb + g)     * 24 + t2]);
            af[mt][1] = *reinterpret_cast<const unsigned*>(&As[(mb + g + 8) * 24 + t2]);
            af[mt][2] = *reinterpret_cast<const unsigned*>(&As[(mb + g)     * 24 + t2 + 8]);
            af[mt][3] = *reinterpret_cast<const unsigned*>(&As[(mb + g + 8) * 24 + t2 + 8]);
        }
#pragma unroll
        for (int nt = 0; nt < 4; nt++) {
            int nb = wn * 32 + nt * 8;
            bf[nt][0] = *reinterpret_cast<const unsigned*>(&Bs[(nb + g) * 24 + t2]);
            bf[nt][1] = *reinterpret_cast<const unsigned*>(&Bs[(nb + g) * 24 + t2 + 8]);
        }
#pragma unroll
        for (int mt = 0; mt < 4; mt++)
#pragma unroll
            for (int nt = 0; nt < 4; nt++)
                mma16816(acc[mt * 4 + nt], af[mt], bf[nt][0], bf[nt][1]);
        __syncthreads();
    }
#pragma unroll
    for (int mt = 0; mt < 4; mt++) {
#pragma unroll
        for (int nt = 0; nt < 4; nt++) {
            int row = rb + wm * 64 + mt * 16 + g;
            int col = cb + wn * 32 + nt * 8 + t2;
            float2 v0 = make_float2(acc[mt * 4 + nt][0], acc[mt * 4 + nt][1]);
            float2 v1 = make_float2(acc[mt * 4 + nt][2], acc[mt * 4 + nt][3]);
            *reinterpret_cast<float2*>(&C[(size_t)row * NN + col]) = v0;
            *reinterpret_cast<float2*>(&C[(size_t)(row + 8) * NN + col]) = v1;
        }
    }
}

// ---- MLP head ----
__global__ void mlp_kernel(const float* __restrict__ emb,
                           const float* __restrict__ W1, const float* __restrict__ b1,
                           const float* __restrict__ W2, const float* __restrict__ b2,
                           float* __restrict__ mu, float* __restrict__ sigma) {
    int n = blockIdx.x, tid = threadIdx.x;
    __shared__ float se[128], sh[32];
    se[tid] = emb[(size_t)n * HD + tid];
    __syncthreads();
    if (tid < 32) {
        float a = b1[tid];
#pragma unroll 8
        for (int k = 0; k < 128; k++) a += se[k] * W1[k * 32 + tid];
        sh[tid] = a > 0.f ? a : 0.f;
    }
    __syncthreads();
    if (tid < 2) {
        float a = b2[tid];
#pragma unroll
        for (int k = 0; k < 32; k++) a += sh[k] * W2[k * 2 + tid];
        if (tid == 0) mu[n] = a; else sigma[n] = a;
    }
}

extern "C" void kernel_launch(void* const* d_in, const int* in_sizes, int n_in,
                              void* d_out, int out_size) {
    const float* x       = (const float*)d_in[0];
    const int*   ei      = (const int*)  d_in[1];
    const float* W_gat   = (const float*)d_in[2];
    const float* att_src = (const float*)d_in[3];
    const float* att_dst = (const float*)d_in[4];
    const float* b_gat   = (const float*)d_in[5];
    const float* W_ih    = (const float*)d_in[6];
    const float* W_hh    = (const float*)d_in[7];
    const float* b_ih    = (const float*)d_in[8];
    const float* b_hh    = (const float*)d_in[9];
    const float* W1      = (const float*)d_in[10];
    const float* b1      = (const float*)d_in[11];
    const float* W2      = (const float*)d_in[12];
    const float* b2      = (const float*)d_in[13];
    float* out = (float*)d_out;

    float* emb   = out;
    float* corr  = out + (size_t)NN * HD;
    float* mu    = corr + (size_t)NN * NN;
    float* sigma = mu + NN;

    void *p_h, *p_g, *p_xg;
    cudaGetSymbolAddress(&p_h,  g_h);
    cudaGetSymbolAddress(&p_g,  g_g);
    cudaGetSymbolAddress(&p_xg, g_xg);

    zero_cnt_kernel<<<(NN + 255) / 256, 256>>>();

    gemm_kernel<false, false><<<dim3(512 / 64, NN / 64), 256>>>(
        x, W_gat, nullptr, nullptr, (float*)p_h, NN, 512, DIN);

    a_kernel<<<NN, 512>>>(att_src, att_dst);

    count_kernel<<<(NE + 255) / 256, 256>>>(ei);
    scan_kernel<<<1, 1024>>>();
    scatter_kernel<<<(NE + 255) / 256, 256>>>(ei);

    gat_agg_kernel<<<NN, 512>>>(b_gat);

    gemm_kernel<true, false><<<dim3(512 / 64, NN / 64), 256>>>(
        (const float*)p_g, W_ih, b_ih, b_hh, (float*)p_xg, NN, 512, HD);

    lstm_kernel<<<1, 512>>>(W_hh, emb);

    xn_pack_kernel<<<NN, 128>>>(emb);

    corr_kernel<<<dim3(NN / 128, NN / 128), 256>>>(corr);

    mlp_kernel<<<NN, 128>>>(emb, W1, b1, W2, b2, mu, sigma);
}

// round 9
// speedup vs baseline: 1.4538x; 1.2023x over previous
#include <cuda_runtime.h>
#include <cuda_fp16.h>
#include <cstdint>

#define NN   4096
#define DIN  128
#define HD   128
#define NE   131072
#define TOTE (NE + NN)
#define NEG  0.2f
#define G4   512

__device__ float g_h[NN * 512];
__device__ float g_asrc[NN * 4];
__device__ float g_adst[NN * 4];
__device__ int   g_cnt[NN];
__device__ int   g_off[NN + 1];
__device__ int   g_cur[NN];
__device__ int   g_srcs[TOTE];
__device__ float g_g[NN * HD];
__device__ float g_xg[(NN + 1) * G4];   // [t][j], j = gate*128+unit; +1 row slack
__device__ __half g_xa[NN * 384];
__device__ __half g_xb[NN * 384];

__device__ __forceinline__ unsigned pack_h2(float x, float y) {
    __half2 h = __floats2half2_rn(x, y);
    return *reinterpret_cast<unsigned*>(&h);
}

__device__ __forceinline__ float tanh_ap(float x) {
    float y;
    asm("tanh.approx.f32 %0, %1;" : "=f"(y) : "f"(x));
    return y;
}

__device__ __forceinline__ void mma16816(float* d, const unsigned* a, unsigned b0, unsigned b1) {
    asm volatile(
        "mma.sync.aligned.m16n8k16.row.col.f32.f16.f16.f32 "
        "{%0,%1,%2,%3}, {%4,%5,%6,%7}, {%8,%9}, {%0,%1,%2,%3};\n"
        : "+f"(d[0]), "+f"(d[1]), "+f"(d[2]), "+f"(d[3])
        : "r"(a[0]), "r"(a[1]), "r"(a[2]), "r"(a[3]), "r"(b0), "r"(b1));
}

__global__ void zero_cnt_kernel() {
    int i = blockIdx.x * blockDim.x + threadIdx.x;
    if (i < NN) g_cnt[i] = 0;
}

// ---- generic tiled SGEMM: C = A(MxK) @ B (+bias +bias2) ----
template <bool TRANSB>
__global__ __launch_bounds__(256)
void gemm_kernel(const float* __restrict__ A, const float* __restrict__ B,
                 const float* __restrict__ bias, const float* __restrict__ bias2,
                 float* __restrict__ C, int M, int N, int K) {
    const int BK = 16;
    __shared__ float As[64][BK + 1];
    __shared__ float Bs[BK][64 + 1];
    int tid = threadIdx.x;
    int tx = tid & 15, ty = tid >> 4;
    int row0 = blockIdx.y * 64, col0 = blockIdx.x * 64;
    float acc[4][4];
#pragma unroll
    for (int r = 0; r < 4; r++)
#pragma unroll
        for (int c = 0; c < 4; c++) acc[r][c] = 0.f;

    for (int k0 = 0; k0 < K; k0 += BK) {
#pragma unroll
        for (int l = 0; l < 4; l++) {
            int idx = tid + l * 256;
            int m = idx >> 4, k = idx & 15;
            As[m][k] = A[(size_t)(row0 + m) * K + (k0 + k)];
        }
#pragma unroll
        for (int l = 0; l < 4; l++) {
            int idx = tid + l * 256;
            if (!TRANSB) {
                int k = idx >> 6, nn = idx & 63;
                Bs[k][nn] = (col0 + nn < N) ? B[(size_t)(k0 + k) * N + (col0 + nn)] : 0.f;
            } else {
                int nn = idx >> 4, k = idx & 15;
                Bs[k][nn] = (col0 + nn < N) ? B[(size_t)(col0 + nn) * K + (k0 + k)] : 0.f;
            }
        }
        __syncthreads();
#pragma unroll
        for (int k = 0; k < BK; k++) {
            float a[4], b[4];
#pragma unroll
            for (int r = 0; r < 4; r++) a[r] = As[ty * 4 + r][k];
#pragma unroll
            for (int c = 0; c < 4; c++) b[c] = Bs[k][tx * 4 + c];
#pragma unroll
            for (int r = 0; r < 4; r++)
#pragma unroll
                for (int c = 0; c < 4; c++) acc[r][c] += a[r] * b[c];
        }
        __syncthreads();
    }
#pragma unroll
    for (int r = 0; r < 4; r++) {
        int row = row0 + ty * 4 + r;
#pragma unroll
        for (int c = 0; c < 4; c++) {
            int col = col0 + tx * 4 + c;
            if (col < N) {
                float v = acc[r][c];
                if (bias)  v += bias[col];
                if (bias2) v += bias2[col];
                C[(size_t)row * N + col] = v;
            }
        }
    }
}

// ---- attention logits ----
__global__ void a_kernel(const float* __restrict__ att_src,
                         const float* __restrict__ att_dst) {
    int n = blockIdx.x, tid = threadIdx.x;
    float hv = g_h[(size_t)n * 512 + tid];
    float ps = hv * att_src[tid];
    float pd = hv * att_dst[tid];
#pragma unroll
    for (int o = 16; o > 0; o >>= 1) {
        ps += __shfl_down_sync(0xffffffffu, ps, o);
        pd += __shfl_down_sync(0xffffffffu, pd, o);
    }
    __shared__ float sps[16], spd[16];
    int w = tid >> 5;
    if ((tid & 31) == 0) { sps[w] = ps; spd[w] = pd; }
    __syncthreads();
    if (tid < 4) {
        g_asrc[n * 4 + tid] = sps[tid * 4] + sps[tid * 4 + 1] + sps[tid * 4 + 2] + sps[tid * 4 + 3];
        g_adst[n * 4 + tid] = spd[tid * 4] + spd[tid * 4 + 1] + spd[tid * 4 + 2] + spd[tid * 4 + 3];
    }
}

__global__ void count_kernel(const int* __restrict__ ei) {
    int i = blockIdx.x * blockDim.x + threadIdx.x;
    if (i < NE) atomicAdd(&g_cnt[ei[NE + i]], 1);
    if (i < NN) atomicAdd(&g_cnt[i], 1);
}

__global__ void scan_kernel() {
    __shared__ int s[1024];
    int tid = threadIdx.x;
    int c[4]; int sum = 0;
#pragma unroll
    for (int i = 0; i < 4; i++) { c[i] = g_cnt[tid * 4 + i]; sum += c[i]; }
    s[tid] = sum;
    __syncthreads();
    for (int off = 1; off < 1024; off <<= 1) {
        int v = s[tid];
        int add = (tid >= off) ? s[tid - off] : 0;
        __syncthreads();
        s[tid] = v + add;
        __syncthreads();
    }
    int run = (tid == 0) ? 0 : s[tid - 1];
#pragma unroll
    for (int i = 0; i < 4; i++) {
        g_off[tid * 4 + i] = run;
        g_cur[tid * 4 + i] = run;
        run += c[i];
    }
    if (tid == 1023) g_off[NN] = run;
}

__global__ void scatter_kernel(const int* __restrict__ ei) {
    int i = blockIdx.x * blockDim.x + threadIdx.x;
    if (i < NE) {
        int d = ei[NE + i];
        g_srcs[atomicAdd(&g_cur[d], 1)] = ei[i];
    }
    if (i < NN) g_srcs[atomicAdd(&g_cur[i], 1)] = i;
}

// ---- GAT softmax + aggregate ----
#define CHUNK 512
__global__ __launch_bounds__(512)
void gat_agg_kernel(const float* __restrict__ b_gat) {
    int n = blockIdx.x, tid = threadIdx.x;
    int beg = g_off[n], end = g_off[n + 1];
    int deg = end - beg;

    __shared__ int   ssrc[CHUNK];
    __shared__ float salpha[CHUNK * 4];
    __shared__ float red[512];
    __shared__ float m_sh[4], rs_sh[4];

    int hh = tid & 3;
    float adst = g_adst[n * 4 + hh];
    float mx = -1e30f;
    for (int e = tid >> 2; e < deg; e += 128) {
        int s = g_srcs[beg + e];
        float v = g_asrc[s * 4 + hh] + adst;
        v = v >= 0.f ? v : NEG * v;
        mx = fmaxf(mx, v);
    }
    red[tid] = mx;
    __syncthreads();
    for (int s = 256; s >= 4; s >>= 1) {
        if (tid < s) red[tid] = fmaxf(red[tid], red[tid + s]);
        __syncthreads();
    }
    if (tid < 4) m_sh[tid] = red[tid];
    __syncthreads();

    float m = m_sh[hh];
    float ssum = 0.f;
    for (int e = tid >> 2; e < deg; e += 128) {
        int s = g_srcs[beg + e];
        float v = g_asrc[s * 4 + hh] + adst;
        v = v >= 0.f ? v : NEG * v;
        ssum += __expf(v - m);
    }
    __syncthreads();
    red[tid] = ssum;
    __syncthreads();
    for (int s = 256; s >= 4; s >>= 1) {
        if (tid < s) red[tid] += red[tid + s];
        __syncthreads();
    }
    if (tid < 4) rs_sh[tid] = 1.0f / (red[tid] + 1e-16f);
    __syncthreads();

    int head = tid >> 7;
    float acc = 0.f;
    float4 ad4 = *reinterpret_cast<const float4*>(&g_adst[n * 4]);
    float m0 = m_sh[0], m1 = m_sh[1], m2 = m_sh[2], m3 = m_sh[3];
    float r0 = rs_sh[0], r1 = rs_sh[1], r2 = rs_sh[2], r3 = rs_sh[3];

    for (int base = 0; base < deg; base += CHUNK) {
        int cnt = min(CHUNK, deg - base);
        __syncthreads();
        if (tid < cnt) {
            int s = g_srcs[beg + base + tid];
            ssrc[tid] = s;
            float4 as4 = *reinterpret_cast<const float4*>(&g_asrc[s * 4]);
            float e0 = as4.x + ad4.x; e0 = e0 >= 0.f ? e0 : NEG * e0;
            float e1 = as4.y + ad4.y; e1 = e1 >= 0.f ? e1 : NEG * e1;
            float e2 = as4.z + ad4.z; e2 = e2 >= 0.f ? e2 : NEG * e2;
            float e3 = as4.w + ad4.w; e3 = e3 >= 0.f ? e3 : NEG * e3;
            salpha[tid * 4 + 0] = __expf(e0 - m0) * r0;
            salpha[tid * 4 + 1] = __expf(e1 - m1) * r1;
            salpha[tid * 4 + 2] = __expf(e2 - m2) * r2;
            salpha[tid * 4 + 3] = __expf(e3 - m3) * r3;
        }
        __syncthreads();
#pragma unroll 4
        for (int e = 0; e < cnt; e++)
            acc += salpha[e * 4 + head] * g_h[(size_t)ssrc[e] * 512 + tid];
    }
    __syncthreads();
    red[tid] = acc;
    __syncthreads();
    if (tid < HD) {
        float s = red[tid] + red[128 + tid] + red[256 + tid] + red[384 + tid];
        float gv = s * 0.25f + b_gat[tid];
        g_g[(size_t)n * HD + tid] = gv > 0.f ? gv : 0.f;
    }
}

// ---- LSTM: r3 structure byte-identical; ONLY change = tanh.approx activations ----
__global__ __launch_bounds__(512, 1)
void lstm_kernel(const float* __restrict__ Whh, float* __restrict__ emb_out) {
    __shared__ __align__(16) __half hsh[128];
    __shared__ float gact[512];
    int j = threadIdx.x;
    int w = j >> 5, lane = j & 31;
    int g = lane >> 2, t2 = (lane & 3) * 2;
    const bool is_g = (w >= 8 && w < 12);

    // Preload A fragments: warp w owns rows [w*32, w*32+32) of W_hh (512x128)
    unsigned a[2][8][4];
#pragma unroll
    for (int mt = 0; mt < 2; mt++) {
        int rb = w * 32 + mt * 16;
#pragma unroll
        for (int kc = 0; kc < 8; kc++) {
            int cb = kc * 16;
            a[mt][kc][0] = pack_h2(Whh[(size_t)(rb + g)     * 128 + cb + t2],     Whh[(size_t)(rb + g)     * 128 + cb + t2 + 1]);
            a[mt][kc][1] = pack_h2(Whh[(size_t)(rb + g + 8) * 128 + cb + t2],     Whh[(size_t)(rb + g + 8) * 128 + cb + t2 + 1]);
            a[mt][kc][2] = pack_h2(Whh[(size_t)(rb + g)     * 128 + cb + t2 + 8], Whh[(size_t)(rb + g)     * 128 + cb + t2 + 9]);
            a[mt][kc][3] = pack_h2(Whh[(size_t)(rb + g + 8) * 128 + cb + t2 + 8], Whh[(size_t)(rb + g + 8) * 128 + cb + t2 + 9]);
        }
    }
    if (j < 64) reinterpret_cast<__half2*>(hsh)[j] = __floats2half2_rn(0.f, 0.f);
    float c = 0.f;
    __syncthreads();

    float xg = g_xg[j];
#pragma unroll 1
    for (int t = 0; t < NN; t++) {
        float d0[4] = {0.f, 0.f, 0.f, 0.f};
        float d1[4] = {0.f, 0.f, 0.f, 0.f};
#pragma unroll
        for (int kc = 0; kc < 8; kc++) {
            unsigned b0 = *reinterpret_cast<const unsigned*>(&hsh[kc * 16 + t2]);
            unsigned b1 = *reinterpret_cast<const unsigned*>(&hsh[kc * 16 + t2 + 8]);
            mma16816(d0, a[0][kc], b0, b1);
            mma16816(d1, a[1][kc], b0, b1);
        }
        float xg_next = g_xg[(size_t)(t + 1) * 512 + j];
        // extract column 0: lane wants row w*32+lane
        int src = (lane & 7) * 4;
        float s00 = __shfl_sync(0xffffffffu, d0[0], src);
        float s02 = __shfl_sync(0xffffffffu, d0[2], src);
        float s10 = __shfl_sync(0xffffffffu, d1[0], src);
        float s12 = __shfl_sync(0xffffffffu, d1[2], src);
        float v = (lane & 16) ? ((lane & 8) ? s12 : s10) : ((lane & 8) ? s02 : s00);
        float z = v + xg;
        float act;
        if (is_g) act = tanh_ap(z);
        else      act = fmaf(0.5f, tanh_ap(0.5f * z), 0.5f);
        gact[j] = act;
        __syncthreads();
        if (j < HD) {
            float gi = gact[j], gf = gact[128 + j], gg = gact[256 + j], go = gact[384 + j];
            c = gf * c + gi * gg;
            float hn = go * tanh_ap(c);
            emb_out[(size_t)t * HD + j] = hn;
            hsh[j] = __float2half_rn(hn);
        }
        __syncthreads();
        xg = xg_next;
    }
}

// ---- normalize + pack split-fp16 for corr ----
__global__ void xn_pack_kernel(const float* __restrict__ emb) {
    int n = blockIdx.x, tid = threadIdx.x;
    float v = emb[(size_t)n * HD + tid];
    float ss = v * v;
#pragma unroll
    for (int o = 16; o > 0; o >>= 1) ss += __shfl_down_sync(0xffffffffu, ss, o);
    __shared__ float sw[4];
    __shared__ float rsh;
    if ((tid & 31) == 0) sw[tid >> 5] = ss;
    __syncthreads();
    if (tid == 0) rsh = 1.0f / fmaxf(sqrtf(sw[0] + sw[1] + sw[2] + sw[3]), 1e-12f);
    __syncthreads();
    float xv = v * rsh;
    __half hi = __float2half_rn(xv);
    __half lo = __float2half_rn(xv - __half2float(hi));
    size_t base = (size_t)n * 384;
    g_xa[base + tid]       = hi;
    g_xa[base + 128 + tid] = lo;
    g_xa[base + 256 + tid] = hi;
    g_xb[base + tid]       = hi;
    g_xb[base + 128 + tid] = hi;
    g_xb[base + 256 + tid] = lo;
}

// ---- corr = xa @ xb^T via HMMA, K=384 (split-fp16 exact) ----
__global__ __launch_bounds__(256, 2)
void corr_kernel(float* __restrict__ C) {
    __shared__ __align__(16) __half As[128 * 24];
    __shared__ __align__(16) __half Bs[128 * 24];
    int tid = threadIdx.x;
    int w = tid >> 5, lane = tid & 31;
    int g = lane >> 2, t2 = (lane & 3) * 2;
    int wm = w >> 2, wn = w & 3;
    int rb = blockIdx.y * 128, cb = blockIdx.x * 128;

    float acc[16][4];
#pragma unroll
    for (int i = 0; i < 16; i++)
#pragma unroll
        for (int q = 0; q < 4; q++) acc[i][q] = 0.f;

    int r = tid >> 1, p = tid & 1;
#pragma unroll 2
    for (int kc = 0; kc < 24; kc++) {
        *reinterpret_cast<uint4*>(&As[r * 24 + p * 8]) =
            *reinterpret_cast<const uint4*>(&g_xa[(size_t)(rb + r) * 384 + kc * 16 + p * 8]);
        *reinterpret_cast<uint4*>(&Bs[r * 24 + p * 8]) =
            *reinterpret_cast<const uint4*>(&g_xb[(size_t)(cb + r) * 384 + kc * 16 + p * 8]);
        __syncthreads();
        unsigned af[4][4], bf[4][2];
#pragma unroll
        for (int mt = 0; mt < 4; mt++) {
            int mb = wm * 64 + mt * 16;
            af[mt][0] = *reinterpret_cast<const unsigned*>(&As[(mb + g)     * 24 + t2]);
            af[mt][1] = *reinterpret_cast<const unsigned*>(&As[(mb + g + 8) * 24 + t2]);
            af[mt][2] = *reinterpret_cast<const unsigned*>(&As[(mb + g)     * 24 + t2 + 8]);
            af[mt][3] = *reinterpret_cast<const unsigned*>(&As[(mb + g + 8) * 24 + t2 + 8]);
        }
#pragma unroll
        for (int nt = 0; nt < 4; nt++) {
            int nb = wn * 32 + nt * 8;
            bf[nt][0] = *reinterpret_cast<const unsigned*>(&Bs[(nb + g) * 24 + t2]);
            bf[nt][1] = *reinterpret_cast<const unsigned*>(&Bs[(nb + g) * 24 + t2 + 8]);
        }
#pragma unroll
        for (int mt = 0; mt < 4; mt++)
#pragma unroll
            for (int nt = 0; nt < 4; nt++)
                mma16816(acc[mt * 4 + nt], af[mt], bf[nt][0], bf[nt][1]);
        __syncthreads();
    }
#pragma unroll
    for (int mt = 0; mt < 4; mt++) {
#pragma unroll
        for (int nt = 0; nt < 4; nt++) {
            int row = rb + wm * 64 + mt * 16 + g;
            int col = cb + wn * 32 + nt * 8 + t2;
            float2 v0 = make_float2(acc[mt * 4 + nt][0], acc[mt * 4 + nt][1]);
            float2 v1 = make_float2(acc[mt * 4 + nt][2], acc[mt * 4 + nt][3]);
            *reinterpret_cast<float2*>(&C[(size_t)row * NN + col]) = v0;
            *reinterpret_cast<float2*>(&C[(size_t)(row + 8) * NN + col]) = v1;
        }
    }
}

// ---- MLP head ----
__global__ void mlp_kernel(const float* __restrict__ emb,
                           const float* __restrict__ W1, const float* __restrict__ b1,
                           const float* __restrict__ W2, const float* __restrict__ b2,
                           float* __restrict__ mu, float* __restrict__ sigma) {
    int n = blockIdx.x, tid = threadIdx.x;
    __shared__ float se[128], sh[32];
    se[tid] = emb[(size_t)n * HD + tid];
    __syncthreads();
    if (tid < 32) {
        float a = b1[tid];
#pragma unroll 8
        for (int k = 0; k < 128; k++) a += se[k] * W1[k * 32 + tid];
        sh[tid] = a > 0.f ? a : 0.f;
    }
    __syncthreads();
    if (tid < 2) {
        float a = b2[tid];
#pragma unroll
        for (int k = 0; k < 32; k++) a += sh[k] * W2[k * 2 + tid];
        if (tid == 0) mu[n] = a; else sigma[n] = a;
    }
}

extern "C" void kernel_launch(void* const* d_in, const int* in_sizes, int n_in,
                              void* d_out, int out_size) {
    const float* x       = (const float*)d_in[0];
    const int*   ei      = (const int*)  d_in[1];
    const float* W_gat   = (const float*)d_in[2];
    const float* att_src = (const float*)d_in[3];
    const float* att_dst = (const float*)d_in[4];
    const float* b_gat   = (const float*)d_in[5];
    const float* W_ih    = (const float*)d_in[6];
    const float* W_hh    = (const float*)d_in[7];
    const float* b_ih    = (const float*)d_in[8];
    const float* b_hh    = (const float*)d_in[9];
    const float* W1      = (const float*)d_in[10];
    const float* b1      = (const float*)d_in[11];
    const float* W2      = (const float*)d_in[12];
    const float* b2      = (const float*)d_in[13];
    float* out = (float*)d_out;

    float* emb   = out;
    float* corr  = out + (size_t)NN * HD;
    float* mu    = corr + (size_t)NN * NN;
    float* sigma = mu + NN;

    void *p_h, *p_g, *p_xg;
    cudaGetSymbolAddress(&p_h,  g_h);
    cudaGetSymbolAddress(&p_g,  g_g);
    cudaGetSymbolAddress(&p_xg, g_xg);

    zero_cnt_kernel<<<(NN + 255) / 256, 256>>>();

    gemm_kernel<false><<<dim3(512 / 64, NN / 64), 256>>>(
        x, W_gat, nullptr, nullptr, (float*)p_h, NN, 512, DIN);

    a_kernel<<<NN, 512>>>(att_src, att_dst);

    count_kernel<<<(NE + 255) / 256, 256>>>(ei);
    scan_kernel<<<1, 1024>>>();
    scatter_kernel<<<(NE + 255) / 256, 256>>>(ei);

    gat_agg_kernel<<<NN, 512>>>(b_gat);

    gemm_kernel<true><<<dim3(512 / 64, NN / 64), 256>>>(
        (const float*)p_g, W_ih, b_ih, b_hh, (float*)p_xg, NN, 512, HD);

    lstm_kernel<<<1, 512>>>(W_hh, emb);

    xn_pack_kernel<<<NN, 128>>>(emb);

    corr_kernel<<<dim3(NN / 128, NN / 128), 256>>>(corr);

    mlp_kernel<<<NN, 128>>>(emb, W1, b1, W2, b2, mu, sigma);
}